// round 13
// baseline (speedup 1.0000x reference)
#include <cuda_runtime.h>
#include <cstdint>

#define S_LEN 1500
#define NPAIR 750
#define NH 8
#define DM 16
#define DFF 128
#define NROWS 3000
#define XELEMS 48000
#define NBLK 144
#define ROWS_PB 21                      // 144*21 = 3024 >= 3000
#define QPB 168                         // queries per attn chunk
#define NCHUNK 9                        // 9*168 >= 1500
#define NSTEP2 24                       // ceil(750/32)
#define ATTN_ELEMS 36000000ull          // 2*8*1500*1500

// SMEM float offsets
#define KV_F    6000                    // kv region: 2*750 float4
#define STAG_F  3008                    // per-warp stag (rows A+B, 12032B)
#define WOFF    (KV_F + 16 * STAG_F)    // 54128: persistent small weights
#define SMEM_F  (WOFF + 1024)           // 55152 floats = 220608 B
// post-phase aliases inside (drained) stag region:
#define SHH_F   KV_F                    // [32*128]
#define SW1_F   (KV_F + 4096)           // [2048]
#define SW2_F   (KV_F + 6144)           // [2048]

// Scratch (no allocations allowed)
__device__ float g_x[XELEMS];
__device__ float g_q[XELEMS];           // [B,H,S,2]
__device__ float g_k[XELEMS];
__device__ float g_v[XELEMS];
__device__ float g_ctx[XELEMS];
__device__ unsigned g_bar;              // grid barrier counter (reset at end)
__device__ unsigned g_done;

__device__ __forceinline__ uint32_t smem_u32(const void* p) {
    uint32_t a;
    asm("{ .reg .u64 t; cvta.to.shared.u64 t, %1; cvt.u32.u64 %0, t; }"
        : "=r"(a) : "l"(p));
    return a;
}
__device__ __forceinline__ float ex2f(float x) {
    float y;
    asm("ex2.approx.f32 %0, %1;" : "=f"(y) : "f"(x));
    return y;
}
// grid-wide barrier: all NBLK blocks co-resident (144 blocks, 1/SM).
__device__ __forceinline__ void grid_bar(unsigned target) {
    __syncthreads();
    if (threadIdx.x == 0) {
        asm volatile("red.release.gpu.global.add.u32 [%0], 1;"
                     :: "l"(&g_bar) : "memory");
        unsigned v;
        do {
            asm volatile("ld.acquire.gpu.global.u32 %0, [%1];"
                         : "=r"(v) : "l"(&g_bar) : "memory");
        } while (v < target);
    }
    __syncthreads();
}

__global__ void __launch_bounds__(512, 1) mono_kernel(
    const float* __restrict__ enc, const float* __restrict__ srcw,
    const float* __restrict__ srcb, const float* __restrict__ Wq,
    const float* __restrict__ Wk, const float* __restrict__ Wv,
    const float* __restrict__ Wo, const float* __restrict__ W1,
    const float* __restrict__ W2, float* __restrict__ out)
{
    extern __shared__ __align__(16) float smem[];
    float4* sk2 = (float4*)smem;                 // [750]
    float4* sv2 = (float4*)(smem + 4 * NPAIR);   // [750]
    float*  stagbase = smem + KV_F;              // [16][STAG_F]
    float*  shh = smem + SHH_F;                  // post sh (stag alias, drained)
    float*  sw1 = smem + SW1_F;                  // post W1 (stag alias)
    float*  sw2 = smem + SW2_F;                  // post W2 (stag alias)
    float*  swo = smem + WOFF;                   // [256]  persistent
    float*  swq = smem + WOFF + 256;             // [256]
    float*  swk = smem + WOFF + 512;             // [256]
    float*  swv = smem + WOFF + 768;             // [256]

    int tid = threadIdx.x;
    int bid = blockIdx.x;
    int warp = tid >> 5, lane = tid & 31;
    int base16 = lane & 16;
    const float qscale = 0.70710678118654752f * 1.44269504088896341f;

    // ---------------- phase 0: embed + layer-0 qkv ----------------
    {
        if (tid < 256) { swq[tid] = Wq[tid]; swk[tid] = Wk[tid]; swv[tid] = Wv[tid]; }
        int r = tid >> 4, d = tid & 15;
        int grow = bid * ROWS_PB + r;
        bool ok = (r < ROWS_PB) && (grow < NROWS);
        float xv = 0.f;
        if (ok) {
            int s = grow % S_LEN;
            const float c = -0.57564627324851148f;   // -ln(10000)/16
            float dv = __expf((float)(d & ~1) * c);
            float ph = (float)s * dv;
            float pe = (d & 1) ? cosf(ph) : sinf(ph);
            xv = enc[grow] * srcw[d] + srcb[d] + pe;
            g_x[grow * DM + d] = xv;
        }
        __syncthreads();
        float xk[16];
#pragma unroll
        for (int k = 0; k < 16; k++) xk[k] = __shfl_sync(0xffffffffu, xv, base16 + k);
        if (ok) {
            float q = 0.f, kk = 0.f, vv = 0.f;
#pragma unroll
            for (int m = 0; m < 16; m++) {
                q  = fmaf(xk[m], swq[m * 16 + d], q);
                kk = fmaf(xk[m], swk[m * 16 + d], kk);
                vv = fmaf(xk[m], swv[m * 16 + d], vv);
            }
            int b = grow / S_LEN, s = grow - b * S_LEN;
            int h = d >> 1, dk = d & 1;
            int o = ((b * NH + h) * S_LEN + s) * 2 + dk;
            g_q[o] = q; g_k[o] = kk; g_v[o] = vv;
        }
    }
    unsigned bar_t = NBLK;
    grid_bar(bar_t);

    for (int l = 0; l < 3; l++) {
        int last = (l == 2);
        // ---------------- attn phase ----------------
        {
            float* attn_out = out + XELEMS + (size_t)l * ATTN_ELEMS;
            int bh = bid / NCHUNK;           // 0..15
            int chunk = bid - bh * NCHUNK;   // 0..8
            const float4* kp4 = (const float4*)(g_k + bh * S_LEN * 2);
            const float4* vp4 = (const float4*)(g_v + bh * S_LEN * 2);
            for (int i = tid; i < NPAIR; i += 512) {
                sk2[i] = kp4[i];
                sv2[i] = vp4[i];
            }
            // prefetch small weights for post_l
            if (tid < 256) swo[tid] = Wo[l * 256 + tid];
            if (!last && tid >= 256 && tid < 512) {
                int t = tid - 256;
                swq[t] = Wq[(l + 1) * 256 + t];
                swk[t] = Wk[(l + 1) * 256 + t];
                swv[t] = Wv[(l + 1) * 256 + t];
            }
            __syncthreads();

            float* stag = stagbase + warp * STAG_F;
            uint32_t sbuf = smem_u32(stag);
            float2* sA = (float2*)stag;              // row A (normalized later)
            float2* sB = (float2*)(stag + S_LEN);    // row B (unnorm -> rescale)
            int b = bh >> 3, h = bh & 7;
            int p0 = (chunk * QPB) >> 1;
            int pend = min(chunk * QPB + QPB, S_LEN) >> 1;

            for (int p = p0 + warp; p < pend; p += 16) {
                int qa = 2 * p;
                float2 qva = ((const float2*)g_q)[bh * S_LEN + qa];
                float2 qvb = ((const float2*)g_q)[bh * S_LEN + qa + 1];
                qva.x *= qscale; qva.y *= qscale;
                qvb.x *= qscale; qvb.y *= qscale;

                // stag (both rows) must be free of the previous pair's TMA,
                // because the main loop writes row B directly.
                if (lane == 0)
                    asm volatile("cp.async.bulk.wait_group.read 0;" ::: "memory");
                __syncwarp();

                float ea0[NSTEP2], ea1[NSTEP2];
                float sa = 0.f, sb = 0.f, ca0 = 0.f, ca1 = 0.f, cb0 = 0.f, cb1 = 0.f;
#pragma unroll
                for (int i = 0; i < NSTEP2; i++) {
                    int j = lane + 32 * i;
                    if (i < NSTEP2 - 1 || j < NPAIR) {
                        float4 kk = sk2[j];
                        float4 vv = sv2[j];
                        float A0 = ex2f(fmaf(qva.x, kk.x, qva.y * kk.y));
                        float A1 = ex2f(fmaf(qva.x, kk.z, qva.y * kk.w));
                        float B0 = ex2f(fmaf(qvb.x, kk.x, qvb.y * kk.y));
                        float B1 = ex2f(fmaf(qvb.x, kk.z, qvb.y * kk.w));
                        sa += A0 + A1; sb += B0 + B1;
                        ca0 = fmaf(A0, vv.x, fmaf(A1, vv.z, ca0));
                        ca1 = fmaf(A0, vv.y, fmaf(A1, vv.w, ca1));
                        cb0 = fmaf(B0, vv.x, fmaf(B1, vv.z, cb0));
                        cb1 = fmaf(B0, vv.y, fmaf(B1, vv.w, cb1));
                        ea0[i] = A0; ea1[i] = A1;
                        sB[j] = make_float2(B0, B1);   // spill B unnormalized
                    }
                }
#pragma unroll
                for (int o = 16; o; o >>= 1) {
                    sa  += __shfl_xor_sync(0xffffffffu, sa,  o);
                    sb  += __shfl_xor_sync(0xffffffffu, sb,  o);
                    ca0 += __shfl_xor_sync(0xffffffffu, ca0, o);
                    ca1 += __shfl_xor_sync(0xffffffffu, ca1, o);
                    cb0 += __shfl_xor_sync(0xffffffffu, cb0, o);
                    cb1 += __shfl_xor_sync(0xffffffffu, cb1, o);
                }
                float ra = 1.0f / sa, rb = 1.0f / sb;

                // stage row A from registers; rescale row B in place
#pragma unroll
                for (int i = 0; i < NSTEP2; i++) {
                    int j = lane + 32 * i;
                    if (i < NSTEP2 - 1 || j < NPAIR) {
                        sA[j] = make_float2(ea0[i] * ra, ea1[i] * ra);
                        float2 t = sB[j];               // same-lane RAW: ordered
                        sB[j] = make_float2(t.x * rb, t.y * rb);
                    }
                }
                __syncwarp();

                if (lane == 0) {
                    asm volatile("fence.proxy.async.shared::cta;" ::: "memory");
                    float* gdst = attn_out + ((size_t)bh * S_LEN + qa) * S_LEN;
                    asm volatile(
                        "cp.async.bulk.global.shared::cta.bulk_group [%0], [%1], %2;"
                        :: "l"(gdst), "r"(sbuf), "r"((uint32_t)(2 * S_LEN * 4)) : "memory");
                    asm volatile("cp.async.bulk.commit_group;" ::: "memory");

                    int basea = (b * S_LEN + qa) * DM + h * 2;
                    g_ctx[basea]          = ca0 * ra;
                    g_ctx[basea + 1]      = ca1 * ra;
                    g_ctx[basea + DM]     = cb0 * rb;
                    g_ctx[basea + DM + 1] = cb1 * rb;
                }
            }
            // drain all TMA: stag region dies here (post aliases it)
            if (lane == 0)
                asm volatile("cp.async.bulk.wait_group 0;" ::: "memory");
        }
        bar_t += NBLK;
        grid_bar(bar_t);

        // ---------------- post phase ----------------
        {
            // big weights into (drained) stag alias
            const float* W1_l = W1 + l * 2048;
            const float* W2_l = W2 + l * 2048;
            for (int i = tid; i < 2048; i += 512) { sw1[i] = W1_l[i]; sw2[i] = W2_l[i]; }

            int r = tid >> 4, d = tid & 15;
            int grow = bid * ROWS_PB + r;
            bool ok = (r < ROWS_PB) && (grow < NROWS);
            float xv = ok ? g_x[grow * DM + d]   : 0.f;
            float cv = ok ? g_ctx[grow * DM + d] : 0.f;

            float s1 = xv;
#pragma unroll
            for (int k = 0; k < 16; k++) {
                float ck = __shfl_sync(0xffffffffu, cv, base16 + k);
                s1 = fmaf(ck, swo[k * 16 + d], s1);
            }
            float mean = s1;
#pragma unroll
            for (int o = 8; o; o >>= 1) mean += __shfl_xor_sync(0xffffffffu, mean, o);
            mean *= (1.0f / 16.0f);
            float dv = s1 - mean;
            float var = dv * dv;
#pragma unroll
            for (int o = 8; o; o >>= 1) var += __shfl_xor_sync(0xffffffffu, var, o);
            var *= (1.0f / 16.0f);
            float t = dv * rsqrtf(var + 1e-5f);

            __syncthreads();   // sw1/sw2 ready

            float tk[16];
#pragma unroll
            for (int k = 0; k < 16; k++) tk[k] = __shfl_sync(0xffffffffu, t, base16 + k);
#pragma unroll
            for (int i = 0; i < 8; i++) {
                int j = d + 16 * i;
                float hv = 0.f;
#pragma unroll
                for (int k = 0; k < 16; k++) hv = fmaf(tk[k], sw1[k * DFF + j], hv);
                shh[r * DFF + j] = fmaxf(hv, 0.f);
            }
            __syncwarp();

            float s2a = t, s2b = 0.f;
#pragma unroll
            for (int j = 0; j < 64; j++) {
                s2a = fmaf(shh[r * DFF + j],      sw2[j * 16 + d],        s2a);
                s2b = fmaf(shh[r * DFF + 64 + j], sw2[(64 + j) * 16 + d], s2b);
            }
            float s2 = s2a + s2b;

            float mean2 = s2;
#pragma unroll
            for (int o = 8; o; o >>= 1) mean2 += __shfl_xor_sync(0xffffffffu, mean2, o);
            mean2 *= (1.0f / 16.0f);
            float dv2 = s2 - mean2;
            float var2 = dv2 * dv2;
#pragma unroll
            for (int o = 8; o; o >>= 1) var2 += __shfl_xor_sync(0xffffffffu, var2, o);
            var2 *= (1.0f / 16.0f);
            float t2 = dv2 * rsqrtf(var2 + 1e-5f);

            if (last) {
                if (ok) out[grow * DM + d] = t2;
            } else {
                if (ok) g_x[grow * DM + d] = t2;
                float x2k[16];
#pragma unroll
                for (int k = 0; k < 16; k++) x2k[k] = __shfl_sync(0xffffffffu, t2, base16 + k);
                if (ok) {
                    float q = 0.f, kk = 0.f, vv = 0.f;
#pragma unroll
                    for (int m = 0; m < 16; m++) {
                        q  = fmaf(x2k[m], swq[m * 16 + d], q);
                        kk = fmaf(x2k[m], swk[m * 16 + d], kk);
                        vv = fmaf(x2k[m], swv[m * 16 + d], vv);
                    }
                    int b = grow / S_LEN, s = grow - b * S_LEN;
                    int h = d >> 1, dk = d & 1;
                    int o = ((b * NH + h) * S_LEN + s) * 2 + dk;
                    g_q[o] = q; g_k[o] = kk; g_v[o] = vv;
                }
            }
        }
        if (l < 2) { bar_t += NBLK; grid_bar(bar_t); }
    }

    // ---------------- reset barrier state for next graph replay ----------------
    __syncthreads();
    if (tid == 0) {
        unsigned v;
        asm volatile("atom.release.gpu.global.add.u32 %0, [%1], 1;"
                     : "=r"(v) : "l"(&g_done) : "memory");
        if (v == NBLK - 1) {
            g_bar = 0;
            g_done = 0;
            __threadfence();
        }
    }
}

// ---------------------------------------------------------------------------
extern "C" void kernel_launch(void* const* d_in, const int* in_sizes, int n_in,
                              void* d_out, int out_size)
{
    const float* enc  = (const float*)d_in[0];
    const float* srcw = (const float*)d_in[1];
    const float* srcb = (const float*)d_in[2];
    const float* Wq   = (const float*)d_in[3];
    const float* Wk   = (const float*)d_in[4];
    const float* Wv   = (const float*)d_in[5];
    const float* Wo   = (const float*)d_in[6];
    const float* W1   = (const float*)d_in[7];
    const float* W2   = (const float*)d_in[8];
    float* out = (float*)d_out;

    const int SMEM_BYTES = SMEM_F * (int)sizeof(float); // 220608
    static int configured = 0;
    if (!configured) {
        cudaFuncSetAttribute(mono_kernel,
                             cudaFuncAttributeMaxDynamicSharedMemorySize, SMEM_BYTES);
        configured = 1;
    }

    mono_kernel<<<NBLK, 512, SMEM_BYTES>>>(enc, srcw, srcb, Wq, Wk, Wv,
                                           Wo, W1, W2, out);
}

// round 14
// speedup vs baseline: 1.0664x; 1.0664x over previous
#include <cuda_runtime.h>
#include <cstdint>

#define S_LEN 1500
#define NPAIR 750
#define NH 8
#define DM 16
#define DFF 128
#define NROWS 3000
#define XELEMS 48000
#define NBLK 144
#define ROWS_PB 21                      // 144*21 = 3024 >= 3000
#define QPB 168                         // queries per attn chunk
#define NCHUNK 9                        // 9*168 >= 1500
#define NSTEP2 24                       // ceil(750/32)
#define ATTN_ELEMS 36000000ull          // 2*8*1500*1500

// SMEM float offsets
#define KV_F    6000                    // kv region: 2*750 float4
#define STAG_F  3008                    // per-warp stag (rows A+B, 12032B)
#define WOFF    (KV_F + 16 * STAG_F)    // 54128: persistent small weights
#define SMEM_F  (WOFF + 1024)           // 55152 floats = 220608 B
// post-phase aliases inside (drained) stag region:
#define SHH_F   KV_F                    // [32*128]
#define SW1_F   (KV_F + 4096)           // [2048]
#define SW2_F   (KV_F + 6144)           // [2048]

// Scratch (no allocations allowed)
__device__ float g_x[XELEMS];
__device__ float g_q[XELEMS];           // [B,H,S,2]
__device__ float g_k[XELEMS];
__device__ float g_v[XELEMS];
__device__ float g_ctx[XELEMS];
__device__ unsigned g_bar;              // grid barrier counter (reset at end)
__device__ unsigned g_done;

__device__ __forceinline__ uint32_t smem_u32(const void* p) {
    uint32_t a;
    asm("{ .reg .u64 t; cvta.to.shared.u64 t, %1; cvt.u32.u64 %0, t; }"
        : "=r"(a) : "l"(p));
    return a;
}
__device__ __forceinline__ float ex2f(float x) {
    float y;
    asm("ex2.approx.f32 %0, %1;" : "=f"(y) : "f"(x));
    return y;
}
// grid-wide barrier: all NBLK blocks co-resident (144 blocks, 1/SM).
__device__ __forceinline__ void grid_bar(unsigned target) {
    __syncthreads();
    if (threadIdx.x == 0) {
        asm volatile("red.release.gpu.global.add.u32 [%0], 1;"
                     :: "l"(&g_bar) : "memory");
        unsigned v;
        do {
            asm volatile("ld.acquire.gpu.global.u32 %0, [%1];"
                         : "=r"(v) : "l"(&g_bar) : "memory");
        } while (v < target);
    }
    __syncthreads();
}

__global__ void __launch_bounds__(512, 1) mono_kernel(
    const float* __restrict__ enc, const float* __restrict__ srcw,
    const float* __restrict__ srcb, const float* __restrict__ Wq,
    const float* __restrict__ Wk, const float* __restrict__ Wv,
    const float* __restrict__ Wo, const float* __restrict__ W1,
    const float* __restrict__ W2, float* __restrict__ out)
{
    extern __shared__ __align__(16) float smem[];
    float4* sk2 = (float4*)smem;                 // [750]
    float4* sv2 = (float4*)(smem + 4 * NPAIR);   // [750]
    float*  stagbase = smem + KV_F;              // [16][STAG_F]
    float*  shh = smem + SHH_F;                  // post sh (stag alias, drained)
    float*  sw1 = smem + SW1_F;                  // post W1 (stag alias)
    float*  sw2 = smem + SW2_F;                  // post W2 (stag alias)
    float*  swo = smem + WOFF;                   // [256]  persistent
    float*  swq = smem + WOFF + 256;             // [256]
    float*  swk = smem + WOFF + 512;             // [256]
    float*  swv = smem + WOFF + 768;             // [256]

    int tid = threadIdx.x;
    int bid = blockIdx.x;
    int warp = tid >> 5, lane = tid & 31;
    int base16 = lane & 16;
    const float qscale = 0.70710678118654752f * 1.44269504088896341f;

    // ---------------- phase 0: embed + layer-0 qkv ----------------
    {
        if (tid < 256) { swq[tid] = Wq[tid]; swk[tid] = Wk[tid]; swv[tid] = Wv[tid]; }
        int r = tid >> 4, d = tid & 15;
        int grow = bid * ROWS_PB + r;
        bool ok = (r < ROWS_PB) && (grow < NROWS);
        float xv = 0.f;
        if (ok) {
            int s = grow % S_LEN;
            const float c = -0.57564627324851148f;   // -ln(10000)/16
            float dv = __expf((float)(d & ~1) * c);
            float ph = (float)s * dv;
            float pe = (d & 1) ? cosf(ph) : sinf(ph);
            xv = enc[grow] * srcw[d] + srcb[d] + pe;
            g_x[grow * DM + d] = xv;
        }
        __syncthreads();
        float xk[16];
#pragma unroll
        for (int k = 0; k < 16; k++) xk[k] = __shfl_sync(0xffffffffu, xv, base16 + k);
        if (ok) {
            float q = 0.f, kk = 0.f, vv = 0.f;
#pragma unroll
            for (int m = 0; m < 16; m++) {
                q  = fmaf(xk[m], swq[m * 16 + d], q);
                kk = fmaf(xk[m], swk[m * 16 + d], kk);
                vv = fmaf(xk[m], swv[m * 16 + d], vv);
            }
            int b = grow / S_LEN, s = grow - b * S_LEN;
            int h = d >> 1, dk = d & 1;
            int o = ((b * NH + h) * S_LEN + s) * 2 + dk;
            g_q[o] = q; g_k[o] = kk; g_v[o] = vv;
        }
    }
    unsigned bar_t = NBLK;
    grid_bar(bar_t);

    for (int l = 0; l < 3; l++) {
        int last = (l == 2);
        // ---------------- attn phase ----------------
        {
            float* attn_out = out + XELEMS + (size_t)l * ATTN_ELEMS;
            int bh = bid / NCHUNK;           // 0..15
            int chunk = bid - bh * NCHUNK;   // 0..8
            const float4* kp4 = (const float4*)(g_k + bh * S_LEN * 2);
            const float4* vp4 = (const float4*)(g_v + bh * S_LEN * 2);
            for (int i = tid; i < NPAIR; i += 512) {
                sk2[i] = kp4[i];
                sv2[i] = vp4[i];
            }
            // prefetch small weights for post_l (persistent region)
            if (tid < 256) swo[tid] = Wo[l * 256 + tid];
            if (!last && tid >= 256 && tid < 512) {
                int t = tid - 256;
                swq[t] = Wq[(l + 1) * 256 + t];
                swk[t] = Wk[(l + 1) * 256 + t];
                swv[t] = Wv[(l + 1) * 256 + t];
            }
            __syncthreads();

            float* stag = stagbase + warp * STAG_F;
            uint32_t sbuf = smem_u32(stag);
            float2* sA = (float2*)stag;              // row A
            float2* sB = (float2*)(stag + S_LEN);    // row B (adjacent in gmem)
            int b = bh >> 3, h = bh & 7;
            int p0 = (chunk * QPB) >> 1;
            int pend = min(chunk * QPB + QPB, S_LEN) >> 1;

            for (int p = p0 + warp; p < pend; p += 16) {
                int qa = 2 * p;
                float2 qva = ((const float2*)g_q)[bh * S_LEN + qa];
                float2 qvb = ((const float2*)g_q)[bh * S_LEN + qa + 1];
                qva.x *= qscale; qva.y *= qscale;
                qvb.x *= qscale; qvb.y *= qscale;

                float ea0[NSTEP2], ea1[NSTEP2], eb0[NSTEP2], eb1[NSTEP2];
                float sa = 0.f, sb = 0.f, ca0 = 0.f, ca1 = 0.f, cb0 = 0.f, cb1 = 0.f;
#pragma unroll
                for (int i = 0; i < NSTEP2; i++) {
                    int j = lane + 32 * i;
                    if (i < NSTEP2 - 1 || j < NPAIR) {
                        float4 kk = sk2[j];
                        float4 vv = sv2[j];
                        float A0 = ex2f(fmaf(qva.x, kk.x, qva.y * kk.y));
                        float A1 = ex2f(fmaf(qva.x, kk.z, qva.y * kk.w));
                        float B0 = ex2f(fmaf(qvb.x, kk.x, qvb.y * kk.y));
                        float B1 = ex2f(fmaf(qvb.x, kk.z, qvb.y * kk.w));
                        sa += A0 + A1; sb += B0 + B1;
                        ca0 = fmaf(A0, vv.x, fmaf(A1, vv.z, ca0));
                        ca1 = fmaf(A0, vv.y, fmaf(A1, vv.w, ca1));
                        cb0 = fmaf(B0, vv.x, fmaf(B1, vv.z, cb0));
                        cb1 = fmaf(B0, vv.y, fmaf(B1, vv.w, cb1));
                        ea0[i] = A0; ea1[i] = A1; eb0[i] = B0; eb1[i] = B1;
                    }
                }
#pragma unroll
                for (int o = 16; o; o >>= 1) {
                    sa  += __shfl_xor_sync(0xffffffffu, sa,  o);
                    sb  += __shfl_xor_sync(0xffffffffu, sb,  o);
                    ca0 += __shfl_xor_sync(0xffffffffu, ca0, o);
                    ca1 += __shfl_xor_sync(0xffffffffu, ca1, o);
                    cb0 += __shfl_xor_sync(0xffffffffu, cb0, o);
                    cb1 += __shfl_xor_sync(0xffffffffu, cb1, o);
                }
                float ra = 1.0f / sa, rb = 1.0f / sb;

                // previous pair's TMA had the whole compute loop to drain
                if (lane == 0)
                    asm volatile("cp.async.bulk.wait_group.read 0;" ::: "memory");
                __syncwarp();
#pragma unroll
                for (int i = 0; i < NSTEP2; i++) {
                    int j = lane + 32 * i;
                    if (i < NSTEP2 - 1 || j < NPAIR) {
                        sA[j] = make_float2(ea0[i] * ra, ea1[i] * ra);
                        sB[j] = make_float2(eb0[i] * rb, eb1[i] * rb);
                    }
                }
                __syncwarp();

                if (lane == 0) {
                    asm volatile("fence.proxy.async.shared::cta;" ::: "memory");
                    float* gdst = attn_out + ((size_t)bh * S_LEN + qa) * S_LEN;
                    asm volatile(
                        "cp.async.bulk.global.shared::cta.bulk_group [%0], [%1], %2;"
                        :: "l"(gdst), "r"(sbuf), "r"((uint32_t)(2 * S_LEN * 4)) : "memory");
                    asm volatile("cp.async.bulk.commit_group;" ::: "memory");

                    int basea = (b * S_LEN + qa) * DM + h * 2;
                    g_ctx[basea]          = ca0 * ra;
                    g_ctx[basea + 1]      = ca1 * ra;
                    g_ctx[basea + DM]     = cb0 * rb;
                    g_ctx[basea + DM + 1] = cb1 * rb;
                }
            }
            // drain all TMA: stag region dies here (post aliases it)
            if (lane == 0)
                asm volatile("cp.async.bulk.wait_group 0;" ::: "memory");
        }
        bar_t += NBLK;
        grid_bar(bar_t);

        // ---------------- post phase ----------------
        {
            // big weights into (drained) stag alias; overlaps s1/LN1 chain
            const float* W1_l = W1 + l * 2048;
            const float* W2_l = W2 + l * 2048;
            for (int i = tid; i < 2048; i += 512) { sw1[i] = W1_l[i]; sw2[i] = W2_l[i]; }

            int r = tid >> 4, d = tid & 15;
            int grow = bid * ROWS_PB + r;
            bool ok = (r < ROWS_PB) && (grow < NROWS);
            float xv = ok ? g_x[grow * DM + d]   : 0.f;
            float cv = ok ? g_ctx[grow * DM + d] : 0.f;

            float s1 = xv;
#pragma unroll
            for (int k = 0; k < 16; k++) {
                float ck = __shfl_sync(0xffffffffu, cv, base16 + k);
                s1 = fmaf(ck, swo[k * 16 + d], s1);
            }
            float mean = s1;
#pragma unroll
            for (int o = 8; o; o >>= 1) mean += __shfl_xor_sync(0xffffffffu, mean, o);
            mean *= (1.0f / 16.0f);
            float dv = s1 - mean;
            float var = dv * dv;
#pragma unroll
            for (int o = 8; o; o >>= 1) var += __shfl_xor_sync(0xffffffffu, var, o);
            var *= (1.0f / 16.0f);
            float t = dv * rsqrtf(var + 1e-5f);

            __syncthreads();   // sw1/sw2 ready

            float tk[16];
#pragma unroll
            for (int k = 0; k < 16; k++) tk[k] = __shfl_sync(0xffffffffu, t, base16 + k);
#pragma unroll
            for (int i = 0; i < 8; i++) {
                int j = d + 16 * i;
                float hv = 0.f;
#pragma unroll
                for (int k = 0; k < 16; k++) hv = fmaf(tk[k], sw1[k * DFF + j], hv);
                shh[r * DFF + j] = fmaxf(hv, 0.f);
            }
            __syncwarp();

            float s2a = t, s2b = 0.f;
#pragma unroll
            for (int j = 0; j < 64; j++) {
                s2a = fmaf(shh[r * DFF + j],      sw2[j * 16 + d],        s2a);
                s2b = fmaf(shh[r * DFF + 64 + j], sw2[(64 + j) * 16 + d], s2b);
            }
            float s2 = s2a + s2b;

            float mean2 = s2;
#pragma unroll
            for (int o = 8; o; o >>= 1) mean2 += __shfl_xor_sync(0xffffffffu, mean2, o);
            mean2 *= (1.0f / 16.0f);
            float dv2 = s2 - mean2;
            float var2 = dv2 * dv2;
#pragma unroll
            for (int o = 8; o; o >>= 1) var2 += __shfl_xor_sync(0xffffffffu, var2, o);
            var2 *= (1.0f / 16.0f);
            float t2 = dv2 * rsqrtf(var2 + 1e-5f);

            if (last) {
                if (ok) out[grow * DM + d] = t2;
            } else {
                if (ok) g_x[grow * DM + d] = t2;
                float x2k[16];
#pragma unroll
                for (int k = 0; k < 16; k++) x2k[k] = __shfl_sync(0xffffffffu, t2, base16 + k);
                if (ok) {
                    float q = 0.f, kk = 0.f, vv = 0.f;
#pragma unroll
                    for (int m = 0; m < 16; m++) {
                        q  = fmaf(x2k[m], swq[m * 16 + d], q);
                        kk = fmaf(x2k[m], swk[m * 16 + d], kk);
                        vv = fmaf(x2k[m], swv[m * 16 + d], vv);
                    }
                    int b = grow / S_LEN, s = grow - b * S_LEN;
                    int h = d >> 1, dk = d & 1;
                    int o = ((b * NH + h) * S_LEN + s) * 2 + dk;
                    g_q[o] = q; g_k[o] = kk; g_v[o] = vv;
                }
            }
        }
        if (l < 2) { bar_t += NBLK; grid_bar(bar_t); }
    }

    // ---------------- reset barrier state for next graph replay ----------------
    __syncthreads();
    if (tid == 0) {
        unsigned v;
        asm volatile("atom.release.gpu.global.add.u32 %0, [%1], 1;"
                     : "=r"(v) : "l"(&g_done) : "memory");
        if (v == NBLK - 1) {
            g_bar = 0;
            g_done = 0;
            __threadfence();
        }
    }
}

// ---------------------------------------------------------------------------
extern "C" void kernel_launch(void* const* d_in, const int* in_sizes, int n_in,
                              void* d_out, int out_size)
{
    const float* enc  = (const float*)d_in[0];
    const float* srcw = (const float*)d_in[1];
    const float* srcb = (const float*)d_in[2];
    const float* Wq   = (const float*)d_in[3];
    const float* Wk   = (const float*)d_in[4];
    const float* Wv   = (const float*)d_in[5];
    const float* Wo   = (const float*)d_in[6];
    const float* W1   = (const float*)d_in[7];
    const float* W2   = (const float*)d_in[8];
    float* out = (float*)d_out;

    const int SMEM_BYTES = SMEM_F * (int)sizeof(float); // 220608
    static int configured = 0;
    if (!configured) {
        cudaFuncSetAttribute(mono_kernel,
                             cudaFuncAttributeMaxDynamicSharedMemorySize, SMEM_BYTES);
        configured = 1;
    }

    mono_kernel<<<NBLK, 512, SMEM_BYTES>>>(enc, srcw, srcb, Wq, Wk, Wv,
                                           Wo, W1, W2, out);
}